// round 15
// baseline (speedup 1.0000x reference)
#include <cuda_runtime.h>

// relu(x @ W^T + b)
// x: [B*N, 2] f32, W: [256, 2] f32 row-major (W[d][i]), b: [256] f32
// out: [B*N, 256] f32.  n_rows = 512000.
//
// R15: single-wave grid (296 blocks = 148 SMs x 2) with CONTIGUOUS per-block
// chunks (~1730 rows each): combines R9's contiguous streaming-store pattern
// (which R12's strided grid-stride lost) with zero wave quantization.
// Inner body identical to R9: broadcast LDG.64 + 8 FFMA chains + two
// STG.128.CS per thread per row.

#define BLOCK_THREADS 512
#define ROWS_PER_BLOCK 16              // 16 warps = 16 concurrent rows
#define GRID_BLOCKS 296                // one full resident wave
#define CHUNK_ROWS 1730                // 296 * 1730 = 512080 >= 512000

__global__ __launch_bounds__(BLOCK_THREADS)
void embeddings_kernel(const float* __restrict__ x,
                       const float* __restrict__ W,
                       const float* __restrict__ b,
                       float* __restrict__ out,
                       int n_rows) {
    int tid  = threadIdx.x;
    int lane = tid & 31;               // 0..31
    int sub  = tid >> 5;               // warp id -> row subgroup

    // Chunk A: cols [lane*4, lane*4+4)  -> W floats [lane*8, lane*8+8) = 2 float4
    // Chunk B: cols A+128               -> W floats offset +256 = +64 float4
    const float4* __restrict__ W4 = reinterpret_cast<const float4*>(W);
    float4 wa0 = __ldg(&W4[lane * 2 + 0]);      // {Wx,Wy} cols A+0, A+1
    float4 wa1 = __ldg(&W4[lane * 2 + 1]);      // cols A+2, A+3
    float4 wb0 = __ldg(&W4[lane * 2 + 64]);     // cols B+0, B+1
    float4 wb1 = __ldg(&W4[lane * 2 + 65]);     // cols B+2, B+3
    const float4* __restrict__ b4 = reinterpret_cast<const float4*>(b);
    float4 ba = __ldg(&b4[lane]);               // bias cols A+0..A+3
    float4 bb = __ldg(&b4[lane + 32]);          // bias cols B+0..B+3

    int block_start = blockIdx.x * CHUNK_ROWS;
    int block_end   = block_start + CHUNK_ROWS;
    if (block_end > n_rows) block_end = n_rows;

    int row0 = block_start + sub;

    const float2* __restrict__ xp = reinterpret_cast<const float2*>(x) + row0;
    float4* __restrict__ opA = reinterpret_cast<float4*>(out) + row0 * 64 + lane;
    float4* __restrict__ opB = opA + 32;        // +128 floats

    #pragma unroll 4
    for (int row = row0; row < block_end; row += ROWS_PER_BLOCK) {
        float2 xx = __ldg(xp);         // one broadcast load per warp per row

        float4 ya, yb;
        ya.x = fmaxf(fmaf(xx.x, wa0.x, fmaf(xx.y, wa0.y, ba.x)), 0.0f);
        ya.y = fmaxf(fmaf(xx.x, wa0.z, fmaf(xx.y, wa0.w, ba.y)), 0.0f);
        ya.z = fmaxf(fmaf(xx.x, wa1.x, fmaf(xx.y, wa1.y, ba.z)), 0.0f);
        ya.w = fmaxf(fmaf(xx.x, wa1.z, fmaf(xx.y, wa1.w, ba.w)), 0.0f);
        yb.x = fmaxf(fmaf(xx.x, wb0.x, fmaf(xx.y, wb0.y, bb.x)), 0.0f);
        yb.y = fmaxf(fmaf(xx.x, wb0.z, fmaf(xx.y, wb0.w, bb.y)), 0.0f);
        yb.z = fmaxf(fmaf(xx.x, wb1.x, fmaf(xx.y, wb1.y, bb.z)), 0.0f);
        yb.w = fmaxf(fmaf(xx.x, wb1.z, fmaf(xx.y, wb1.w, bb.w)), 0.0f);

        __stcs(opA, ya);               // two independent coalesced streaming stores
        __stcs(opB, yb);

        xp  += ROWS_PER_BLOCK;
        opA += ROWS_PER_BLOCK * 64;
        opB += ROWS_PER_BLOCK * 64;
    }
}

extern "C" void kernel_launch(void* const* d_in, const int* in_sizes, int n_in,
                              void* d_out, int out_size) {
    const float* x = (const float*)d_in[0];   // [B, N, 2]
    const float* W = (const float*)d_in[1];   // [256, 2]
    const float* b = (const float*)d_in[2];   // [256]
    float* out = (float*)d_out;               // [B, N, 256]

    int n_rows = in_sizes[0] / 2;             // B*N = 512000

    embeddings_kernel<<<GRID_BLOCKS, BLOCK_THREADS>>>(x, W, b, out, n_rows);
}

// round 16
// speedup vs baseline: 1.1525x; 1.1525x over previous
#include <cuda_runtime.h>

// relu(x @ W^T + b)
// x: [B*N, 2] f32, W: [256, 2] f32 row-major (W[d][i]), b: [256] f32
// out: [B*N, 256] f32.  n_rows = 512000.
//
// R16: R9 body (best, 79.9us) with finer block granularity: ITERS 16 -> 8,
// 128 rows/block, grid = 4000. Probes the dynamic-load-balance model that
// explained the persistent-grid regressions (many short blocks absorb
// per-CTA time spread via work-stealing). Everything else identical to R9.

#define BLOCK_THREADS 512
#define ROWS_PER_BLOCK 16              // 16 warps = 16 concurrent rows
#define ITERS 8                        // -> 128 rows per block, grid = 4000

__global__ __launch_bounds__(BLOCK_THREADS)
void embeddings_kernel(const float* __restrict__ x,
                       const float* __restrict__ W,
                       const float* __restrict__ b,
                       float* __restrict__ out,
                       int n_rows) {
    int tid  = threadIdx.x;
    int lane = tid & 31;               // 0..31
    int sub  = tid >> 5;               // warp id -> row subgroup

    // Chunk A: cols [lane*4, lane*4+4)  -> W floats [lane*8, lane*8+8) = 2 float4
    // Chunk B: cols A+128               -> W floats offset +256 = +64 float4
    const float4* __restrict__ W4 = reinterpret_cast<const float4*>(W);
    float4 wa0 = __ldg(&W4[lane * 2 + 0]);      // {Wx,Wy} cols A+0, A+1
    float4 wa1 = __ldg(&W4[lane * 2 + 1]);      // cols A+2, A+3
    float4 wb0 = __ldg(&W4[lane * 2 + 64]);     // cols B+0, B+1
    float4 wb1 = __ldg(&W4[lane * 2 + 65]);     // cols B+2, B+3
    const float4* __restrict__ b4 = reinterpret_cast<const float4*>(b);
    float4 ba = __ldg(&b4[lane]);               // bias cols A+0..A+3
    float4 bb = __ldg(&b4[lane + 32]);          // bias cols B+0..B+3

    int row0 = blockIdx.x * (ROWS_PER_BLOCK * ITERS) + sub;

    const float2* __restrict__ xp = reinterpret_cast<const float2*>(x) + row0;
    float4* __restrict__ opA = reinterpret_cast<float4*>(out) + row0 * 64 + lane;
    float4* __restrict__ opB = opA + 32;        // +128 floats

    int rows_left = n_rows - row0;

    #pragma unroll 4
    for (int i = 0; i < ITERS; i++) {
        if (i * ROWS_PER_BLOCK >= rows_left) break;

        float2 xx = __ldg(xp);         // one broadcast load per warp per row

        float4 ya, yb;
        ya.x = fmaxf(fmaf(xx.x, wa0.x, fmaf(xx.y, wa0.y, ba.x)), 0.0f);
        ya.y = fmaxf(fmaf(xx.x, wa0.z, fmaf(xx.y, wa0.w, ba.y)), 0.0f);
        ya.z = fmaxf(fmaf(xx.x, wa1.x, fmaf(xx.y, wa1.y, ba.z)), 0.0f);
        ya.w = fmaxf(fmaf(xx.x, wa1.z, fmaf(xx.y, wa1.w, ba.w)), 0.0f);
        yb.x = fmaxf(fmaf(xx.x, wb0.x, fmaf(xx.y, wb0.y, bb.x)), 0.0f);
        yb.y = fmaxf(fmaf(xx.x, wb0.z, fmaf(xx.y, wb0.w, bb.y)), 0.0f);
        yb.z = fmaxf(fmaf(xx.x, wb1.x, fmaf(xx.y, wb1.y, bb.z)), 0.0f);
        yb.w = fmaxf(fmaf(xx.x, wb1.z, fmaf(xx.y, wb1.w, bb.w)), 0.0f);

        __stcs(opA, ya);               // two independent coalesced streaming stores
        __stcs(opB, yb);

        xp  += ROWS_PER_BLOCK;
        opA += ROWS_PER_BLOCK * 64;
        opB += ROWS_PER_BLOCK * 64;
    }
}

extern "C" void kernel_launch(void* const* d_in, const int* in_sizes, int n_in,
                              void* d_out, int out_size) {
    const float* x = (const float*)d_in[0];   // [B, N, 2]
    const float* W = (const float*)d_in[1];   // [256, 2]
    const float* b = (const float*)d_in[2];   // [256]
    float* out = (float*)d_out;               // [B, N, 256]

    int n_rows = in_sizes[0] / 2;             // B*N = 512000

    int rows_per_block = ROWS_PER_BLOCK * ITERS;   // 128
    int grid = (n_rows + rows_per_block - 1) / rows_per_block;   // 4000
    embeddings_kernel<<<grid, BLOCK_THREADS>>>(x, W, b, out, n_rows);
}

// round 17
// speedup vs baseline: 1.1827x; 1.0262x over previous
#include <cuda_runtime.h>

// relu(x @ W^T + b)
// x: [B*N, 2] f32, W: [256, 2] f32 row-major (W[d][i]), b: [256] f32
// out: [B*N, 256] f32.  n_rows = 512000.
//
// R17: R16 body (best, 77.8us) with ITERS 8 -> 4: 64 rows/block, grid=8000.
// Continues the confirmed monotone granularity trend (finer blocks -> better
// dynamic load balance across SMs). Everything else identical to R16.

#define BLOCK_THREADS 512
#define ROWS_PER_BLOCK 16              // 16 warps = 16 concurrent rows
#define ITERS 4                        // -> 64 rows per block, grid = 8000

__global__ __launch_bounds__(BLOCK_THREADS)
void embeddings_kernel(const float* __restrict__ x,
                       const float* __restrict__ W,
                       const float* __restrict__ b,
                       float* __restrict__ out,
                       int n_rows) {
    int tid  = threadIdx.x;
    int lane = tid & 31;               // 0..31
    int sub  = tid >> 5;               // warp id -> row subgroup

    // Chunk A: cols [lane*4, lane*4+4)  -> W floats [lane*8, lane*8+8) = 2 float4
    // Chunk B: cols A+128               -> W floats offset +256 = +64 float4
    const float4* __restrict__ W4 = reinterpret_cast<const float4*>(W);
    float4 wa0 = __ldg(&W4[lane * 2 + 0]);      // {Wx,Wy} cols A+0, A+1
    float4 wa1 = __ldg(&W4[lane * 2 + 1]);      // cols A+2, A+3
    float4 wb0 = __ldg(&W4[lane * 2 + 64]);     // cols B+0, B+1
    float4 wb1 = __ldg(&W4[lane * 2 + 65]);     // cols B+2, B+3
    const float4* __restrict__ b4 = reinterpret_cast<const float4*>(b);
    float4 ba = __ldg(&b4[lane]);               // bias cols A+0..A+3
    float4 bb = __ldg(&b4[lane + 32]);          // bias cols B+0..B+3

    int row0 = blockIdx.x * (ROWS_PER_BLOCK * ITERS) + sub;

    const float2* __restrict__ xp = reinterpret_cast<const float2*>(x) + row0;
    float4* __restrict__ opA = reinterpret_cast<float4*>(out) + row0 * 64 + lane;
    float4* __restrict__ opB = opA + 32;        // +128 floats

    int rows_left = n_rows - row0;

    #pragma unroll 4
    for (int i = 0; i < ITERS; i++) {
        if (i * ROWS_PER_BLOCK >= rows_left) break;

        float2 xx = __ldg(xp);         // one broadcast load per warp per row

        float4 ya, yb;
        ya.x = fmaxf(fmaf(xx.x, wa0.x, fmaf(xx.y, wa0.y, ba.x)), 0.0f);
        ya.y = fmaxf(fmaf(xx.x, wa0.z, fmaf(xx.y, wa0.w, ba.y)), 0.0f);
        ya.z = fmaxf(fmaf(xx.x, wa1.x, fmaf(xx.y, wa1.y, ba.z)), 0.0f);
        ya.w = fmaxf(fmaf(xx.x, wa1.z, fmaf(xx.y, wa1.w, ba.w)), 0.0f);
        yb.x = fmaxf(fmaf(xx.x, wb0.x, fmaf(xx.y, wb0.y, bb.x)), 0.0f);
        yb.y = fmaxf(fmaf(xx.x, wb0.z, fmaf(xx.y, wb0.w, bb.y)), 0.0f);
        yb.z = fmaxf(fmaf(xx.x, wb1.x, fmaf(xx.y, wb1.y, bb.z)), 0.0f);
        yb.w = fmaxf(fmaf(xx.x, wb1.z, fmaf(xx.y, wb1.w, bb.w)), 0.0f);

        __stcs(opA, ya);               // two independent coalesced streaming stores
        __stcs(opB, yb);

        xp  += ROWS_PER_BLOCK;
        opA += ROWS_PER_BLOCK * 64;
        opB += ROWS_PER_BLOCK * 64;
    }
}

extern "C" void kernel_launch(void* const* d_in, const int* in_sizes, int n_in,
                              void* d_out, int out_size) {
    const float* x = (const float*)d_in[0];   // [B, N, 2]
    const float* W = (const float*)d_in[1];   // [256, 2]
    const float* b = (const float*)d_in[2];   // [256]
    float* out = (float*)d_out;               // [B, N, 256]

    int n_rows = in_sizes[0] / 2;             // B*N = 512000

    int rows_per_block = ROWS_PER_BLOCK * ITERS;   // 64
    int grid = (n_rows + rows_per_block - 1) / rows_per_block;   // 8000
    embeddings_kernel<<<grid, BLOCK_THREADS>>>(x, W, b, out, n_rows);
}